// round 6
// baseline (speedup 1.0000x reference)
#include <cuda_runtime.h>
#include <cuda_fp16.h>

// Problem constants
constexpr int B    = 2;
constexpr int Hdim = 128;
constexpr int Wdim = 128;
constexpr int C    = 64;     // channels == BIN == 64
constexpr int KS   = 5;
constexpr int PAD  = KS / 2; // 2

// Tiling: 16x16 pixel tile, 2 threads per pixel (channel halves) = 512 threads
constexpr int TXN = 16;
constexpr int TYN = 16;
constexpr int HX  = TXN + 2 * PAD; // 20
constexpr int HY  = TYN + 2 * PAD; // 20
constexpr int NV  = HX * HY;       // 400 vectors

constexpr int NTHREADS = TXN * TYN * 2; // 512

// ref (fp32): stride 68 floats -> lane word-stride 4 mod 32, conflict-free LDS.128
constexpr int VSTRIDE_R = C + 4;   // 68 floats
// val (fp16): stride 72 halves (=36 words) -> same conflict-free pattern
constexpr int VSTRIDE_V = C + 8;   // 72 halves

constexpr int SMEM_REF_BYTES = NV * VSTRIDE_R * 4;  // 108,800
constexpr int SMEM_VAL_BYTES = NV * VSTRIDE_V * 2;  //  57,600
constexpr int SMEM_BYTES     = SMEM_REF_BYTES + SMEM_VAL_BYTES; // 166,400

__global__ __launch_bounds__(NTHREADS)
void refloc_kernel(const float* __restrict__ main_t,
                   const float* __restrict__ ref_t,
                   const float* __restrict__ val_t,
                   float* __restrict__ out)
{
    extern __shared__ float s[];
    float*   s_ref = s;
    __half*  s_val = reinterpret_cast<__half*>(s + NV * VSTRIDE_R);

    // Block (16, 2, 16): lanes 0-15 = 16 pixels (half 0), lanes 16-31 = same
    // pixels (half 1) -> partner exchange is shfl_xor(16) within the warp.
    const int tx  = threadIdx.x;             // pixel x, 0..15
    const int hz  = threadIdx.y;             // channel half, 0..1
    const int ty  = threadIdx.z;             // pixel y, 0..15
    const int tid = tx + TXN * hz + TXN * 2 * ty; // 0..511
    const int x0  = blockIdx.x * TXN;
    const int y0  = blockIdx.y * TYN;
    const int b   = blockIdx.z;

    // ---- Stage ref tile (fp32, halo, zero padded) ----
    for (int idx = tid; idx < NV * 16; idx += NTHREADS) {
        const int c4  = idx & 15;
        const int v   = idx >> 4;
        const int col = v % HX;
        const int row = v / HX;
        const int gx  = x0 + col - PAD;
        const int gy  = y0 + row - PAD;
        float4 rv = make_float4(0.f, 0.f, 0.f, 0.f);
        if ((unsigned)gx < (unsigned)Wdim && (unsigned)gy < (unsigned)Hdim) {
            const long base = ((((long)b * Hdim + gy) * Wdim + gx) * C) + c4 * 4;
            rv = *reinterpret_cast<const float4*>(ref_t + base);
        }
        *reinterpret_cast<float4*>(s_ref + v * VSTRIDE_R + c4 * 4) = rv;
    }

    // ---- Stage value tile (fp16, halo, zero padded) ----
    for (int idx = tid; idx < NV * 8; idx += NTHREADS) {
        const int c8  = idx & 7;             // 8-float chunk
        const int v   = idx >> 3;
        const int col = v % HX;
        const int row = v / HX;
        const int gx  = x0 + col - PAD;
        const int gy  = y0 + row - PAD;
        uint4 pk = make_uint4(0u, 0u, 0u, 0u);
        if ((unsigned)gx < (unsigned)Wdim && (unsigned)gy < (unsigned)Hdim) {
            const long base = ((((long)b * Hdim + gy) * Wdim + gx) * C) + c8 * 8;
            const float4 a = *reinterpret_cast<const float4*>(val_t + base);
            const float4 c = *reinterpret_cast<const float4*>(val_t + base + 4);
            __half2 h0 = __floats2half2_rn(a.x, a.y);
            __half2 h1 = __floats2half2_rn(a.z, a.w);
            __half2 h2 = __floats2half2_rn(c.x, c.y);
            __half2 h3 = __floats2half2_rn(c.z, c.w);
            pk.x = *reinterpret_cast<unsigned*>(&h0);
            pk.y = *reinterpret_cast<unsigned*>(&h1);
            pk.z = *reinterpret_cast<unsigned*>(&h2);
            pk.w = *reinterpret_cast<unsigned*>(&h3);
        }
        *reinterpret_cast<uint4*>(s_val + v * VSTRIDE_V + c8 * 8) = pk;
    }
    __syncthreads();

    const int x = x0 + tx;
    const int y = y0 + ty;
    const long pxbase = (((long)b * Hdim + y) * Wdim + x) * C;

    // ---- Load this thread's half of the main (query) vector: 32 channels ----
    float4 m[8];
    const float4* mp = reinterpret_cast<const float4*>(main_t + pxbase + hz * 32);
#pragma unroll
    for (int c = 0; c < 8; c++) m[c] = mp[c];

    // ---- Partial scores over 32 channels for all 25 patches ----
    float sc[KS * KS];
#pragma unroll
    for (int i = 0; i < KS; i++) {
#pragma unroll
        for (int j = 0; j < KS; j++) {
            const float* rp = s_ref + ((ty + i) * HX + (tx + j)) * VSTRIDE_R + hz * 32;
            float a0 = 0.f, a1 = 0.f, a2 = 0.f, a3 = 0.f;
#pragma unroll
            for (int c = 0; c < 8; c++) {
                const float4 r = *reinterpret_cast<const float4*>(rp + c * 4);
                a0 = fmaf(r.x, m[c].x, a0);
                a1 = fmaf(r.y, m[c].y, a1);
                a2 = fmaf(r.z, m[c].z, a2);
                a3 = fmaf(r.w, m[c].w, a3);
            }
            sc[i * KS + j] = (a0 + a1) + (a2 + a3);
        }
    }

    // ---- Combine channel halves: partner is lane^16 (same pixel, other half) ----
#pragma unroll
    for (int p = 0; p < KS * KS; p++) {
        sc[p] += __shfl_xor_sync(0xffffffffu, sc[p], 16);
    }

    // ---- Softmax over 25 (computed redundantly in both halves, identical) ----
    float mx = sc[0];
#pragma unroll
    for (int p = 1; p < KS * KS; p++) mx = fmaxf(mx, sc[p]);
    float sum = 0.f;
#pragma unroll
    for (int p = 0; p < KS * KS; p++) { sc[p] = __expf(sc[p] - mx); sum += sc[p]; }
    const float inv = 1.0f / sum;

    // ---- Weighted sum: this thread accumulates its 32 BIN channels ----
    float2 o[16];
#pragma unroll
    for (int c = 0; c < 16; c++) o[c] = make_float2(0.f, 0.f);
#pragma unroll
    for (int i = 0; i < KS; i++) {
#pragma unroll
        for (int j = 0; j < KS; j++) {
            const float w = sc[i * KS + j] * inv;
            const uint4* vp = reinterpret_cast<const uint4*>(
                s_val + ((ty + i) * HX + (tx + j)) * VSTRIDE_V + hz * 32);
#pragma unroll
            for (int c = 0; c < 4; c++) {
                const uint4 pk = vp[c];
                const float2 f0 = __half22float2(*reinterpret_cast<const __half2*>(&pk.x));
                const float2 f1 = __half22float2(*reinterpret_cast<const __half2*>(&pk.y));
                const float2 f2 = __half22float2(*reinterpret_cast<const __half2*>(&pk.z));
                const float2 f3 = __half22float2(*reinterpret_cast<const __half2*>(&pk.w));
                o[c * 4 + 0].x = fmaf(w, f0.x, o[c * 4 + 0].x);
                o[c * 4 + 0].y = fmaf(w, f0.y, o[c * 4 + 0].y);
                o[c * 4 + 1].x = fmaf(w, f1.x, o[c * 4 + 1].x);
                o[c * 4 + 1].y = fmaf(w, f1.y, o[c * 4 + 1].y);
                o[c * 4 + 2].x = fmaf(w, f2.x, o[c * 4 + 2].x);
                o[c * 4 + 2].y = fmaf(w, f2.y, o[c * 4 + 2].y);
                o[c * 4 + 3].x = fmaf(w, f3.x, o[c * 4 + 3].x);
                o[c * 4 + 3].y = fmaf(w, f3.y, o[c * 4 + 3].y);
            }
        }
    }

    // ---- Store this thread's 32 output channels ----
    float4* op = reinterpret_cast<float4*>(out + pxbase + hz * 32);
#pragma unroll
    for (int c = 0; c < 8; c++) {
        op[c] = make_float4(o[c * 2].x, o[c * 2].y, o[c * 2 + 1].x, o[c * 2 + 1].y);
    }
}

extern "C" void kernel_launch(void* const* d_in, const int* in_sizes, int n_in,
                              void* d_out, int out_size)
{
    const float* main_t = (const float*)d_in[0];
    const float* ref_t  = (const float*)d_in[1];
    const float* val_t  = (const float*)d_in[2];
    float* out = (float*)d_out;

    cudaFuncSetAttribute(refloc_kernel,
                         cudaFuncAttributeMaxDynamicSharedMemorySize, SMEM_BYTES);

    dim3 grid(Wdim / TXN, Hdim / TYN, B);
    dim3 block(TXN, 2, TYN);
    refloc_kernel<<<grid, block, SMEM_BYTES>>>(main_t, ref_t, val_t, out);
}